// round 6
// baseline (speedup 1.0000x reference)
#include <cuda_runtime.h>
#include <cuda_fp16.h>

#define NUM_ENTITIES 500000
#define NUM_RELATIONS 100
#define D 64
#define M 256
#define NTHREADS 256
#define NWARPS 8
#define NQ 32   // quarter-warps per CTA

// fp16 mirrors: entity table scaled by 256 (64 MB, L2-resident), relation table unscaled
__device__ __half g_entH[(size_t)NUM_ENTITIES * D];
__device__ __half g_relH[NUM_RELATIONS * D];

__global__ void convert_kernel(const float* __restrict__ ent, const float* __restrict__ rel) {
    // 15625 blocks * 256 threads * 8 elems = 32,000,000 = NUM_ENTITIES*D exactly
    size_t base = ((size_t)blockIdx.x * 256 + threadIdx.x) * 8;
    float4 a = __ldcs((const float4*)(ent + base));
    float4 b = __ldcs((const float4*)(ent + base + 4));
    __half2 p0 = __floats2half2_rn(a.x * 256.0f, a.y * 256.0f);
    __half2 p1 = __floats2half2_rn(a.z * 256.0f, a.w * 256.0f);
    __half2 p2 = __floats2half2_rn(b.x * 256.0f, b.y * 256.0f);
    __half2 p3 = __floats2half2_rn(b.z * 256.0f, b.w * 256.0f);
    uint4 pk;
    pk.x = *(unsigned*)&p0; pk.y = *(unsigned*)&p1;
    pk.z = *(unsigned*)&p2; pk.w = *(unsigned*)&p3;
    *(uint4*)(g_entH + base) = pk;
    if (blockIdx.x == 0) {
        for (int i = threadIdx.x; i < NUM_RELATIONS * D; i += 256)
            g_relH[i] = __float2half(rel[i]);
    }
}

__device__ __forceinline__ uint4 ldcg_u4(const void* p) {
    uint4 v;
    asm volatile("ld.global.cg.v4.u32 {%0,%1,%2,%3}, [%4];"
                 : "=r"(v.x), "=r"(v.y), "=r"(v.z), "=r"(v.w) : "l"(p));
    return v;
}

__device__ __forceinline__ void h8_to_f8(uint4 u, float* f) {
    float2 a = __half22float2(*reinterpret_cast<__half2*>(&u.x));
    float2 b = __half22float2(*reinterpret_cast<__half2*>(&u.y));
    float2 c = __half22float2(*reinterpret_cast<__half2*>(&u.z));
    float2 d = __half22float2(*reinterpret_cast<__half2*>(&u.w));
    f[0]=a.x; f[1]=a.y; f[2]=b.x; f[3]=b.y; f[4]=c.x; f[5]=c.y; f[6]=d.x; f[7]=d.y;
}

__global__ __launch_bounds__(NTHREADS, 4)
void ripplenet_kernel(const int* __restrict__ item_ids,
                      const int* __restrict__ h0, const int* __restrict__ r0, const int* __restrict__ t0,
                      const int* __restrict__ h1, const int* __restrict__ r1, const int* __restrict__ t1,
                      const float* __restrict__ ent,
                      const float* __restrict__ W0, const float* __restrict__ W1,
                      float* __restrict__ out)
{
    const int b    = blockIdx.x;
    const int tid  = threadIdx.x;
    const int lane = tid & 31;
    const int w    = tid >> 5;
    const int q    = lane >> 3;     // quarter-warp id within warp (slot offset)
    const int ql   = lane & 7;      // lane within quarter: dims [8*ql, 8*ql+8)

    __shared__ __align__(16) float s_item[D];
    __shared__ __align__(16) float s_x[D];
    __shared__ int   s_hidx[M];
    __shared__ int   s_ridx[M];
    __shared__ int   s_tidx[M];
    __shared__ float s_esum[NQ];
    __shared__ __align__(16) float s_o[NQ][D];

    // load item embedding (fp32 original — exact)
    if (tid < D) {
        size_t row = (size_t)item_ids[b] * D;
        s_item[tid] = ent[row + tid];
    }

    for (int hop = 0; hop < 2; hop++) {
        const int* hI = hop ? h1 : h0;
        const int* rI = hop ? r1 : r0;
        const int* tI = hop ? t1 : t0;
        const float* W = hop ? W1 : W0;

        // stage indices coalesced
        s_hidx[tid] = hI[(size_t)b * M + tid];
        s_ridx[tid] = rI[(size_t)b * M + tid];
        s_tidx[tid] = tI[(size_t)b * M + tid];
        __syncthreads();

        // per-lane item chunk (8 dims), pre-scaled by 2^-8 to undo ent scaling
        float itv[8];
        #pragma unroll
        for (int j = 0; j < 8; j++) itv[j] = s_item[8 * ql + j] * 0.00390625f;

        // ---- fused: logits + streaming (unnormalized) softmax + t-accumulate ----
        // quarter-warp per slot; each gather is one LDG.128 / 8 lanes = 1 wavefront.
        float acc[8] = {0,0,0,0,0,0,0,0};
        float esum = 0.0f;
        #pragma unroll 4
        for (int i = w; i < M / 4; i += NWARPS) {
            int m = 4 * i + q;
            uint4 tvp = ldcg_u4(g_entH + (size_t)s_tidx[m] * D + 8 * ql);
            uint4 hvp = ldcg_u4(g_entH + (size_t)s_hidx[m] * D + 8 * ql);
            uint4 rvp = *(const uint4*)(g_relH + s_ridx[m] * D + 8 * ql);
            float hv[8], rv[8], tv[8];
            h8_to_f8(hvp, hv);
            h8_to_f8(rvp, rv);
            float p = 0.0f;
            #pragma unroll
            for (int j = 0; j < 8; j++) p += hv[j] * rv[j] * itv[j];
            #pragma unroll
            for (int s = 4; s; s >>= 1) p += __shfl_xor_sync(0xffffffffu, p, s);
            float e = __expf(p);   // |logit| << 1 — no max-shift needed
            h8_to_f8(tvp, tv);
            esum += e;
            #pragma unroll
            for (int j = 0; j < 8; j++) acc[j] += e * tv[j];
        }
        *(float4*)(&s_o[4 * w + q][8 * ql])     = make_float4(acc[0], acc[1], acc[2], acc[3]);
        *(float4*)(&s_o[4 * w + q][8 * ql + 4]) = make_float4(acc[4], acc[5], acc[6], acc[7]);
        if (ql == 0) s_esum[4 * w + q] = esum;
        __syncthreads();

        // ---- x = item + o_unnorm / (sum_exp * 256) ----
        if (tid < D) {
            float o = 0.0f;
            #pragma unroll
            for (int g = 0; g < NQ; g++) o += s_o[g][tid];
            float es = 0.0f;
            #pragma unroll
            for (int g = 0; g < NQ; g++) es += s_esum[g];
            s_x[tid] = s_item[tid] + o * (0.00390625f / es);
        }
        __syncthreads();

        // ---- item = x @ W^T : item[j] = sum_i x[i] * W[j*D + i] ----
        if (tid < D) {
            const float4* Wr = (const float4*)(W + tid * D);
            float a = 0.0f;
            #pragma unroll
            for (int i = 0; i < D / 4; i++) {
                float4 wv = __ldg(Wr + i);
                a += s_x[4*i]   * wv.x + s_x[4*i+1] * wv.y
                   + s_x[4*i+2] * wv.z + s_x[4*i+3] * wv.w;
            }
            s_item[tid] = a;
        }
        __syncthreads();
    }

    // ---- final: out[b] = sum_d item[d] ----
    if (w == 0) {
        float v = s_item[lane] + s_item[lane + 32];
        #pragma unroll
        for (int s = 16; s; s >>= 1) v += __shfl_xor_sync(0xffffffffu, v, s);
        if (lane == 0) out[b] = v;
    }
}

extern "C" void kernel_launch(void* const* d_in, const int* in_sizes, int n_in,
                              void* d_out, int out_size)
{
    const int*   item_ids = (const int*)d_in[0];
    const int*   h0       = (const int*)d_in[1];
    const int*   r0       = (const int*)d_in[2];
    const int*   t0       = (const int*)d_in[3];
    const int*   h1       = (const int*)d_in[4];
    const int*   r1       = (const int*)d_in[5];
    const int*   t1       = (const int*)d_in[6];
    const float* ent      = (const float*)d_in[7];
    const float* rel      = (const float*)d_in[8];
    const float* W0       = (const float*)d_in[9];
    const float* W1       = (const float*)d_in[10];
    float*       out      = (float*)d_out;

    convert_kernel<<<15625, 256>>>(ent, rel);
    ripplenet_kernel<<<4096, NTHREADS>>>(item_ids, h0, r0, t0, h1, r1, t1,
                                         ent, W0, W1, out);
}

// round 7
// speedup vs baseline: 1.5038x; 1.5038x over previous
#include <cuda_runtime.h>
#include <cuda_fp16.h>

#define NUM_ENTITIES 500000
#define NUM_RELATIONS 100
#define D 64
#define M 256
#define NTHREADS 256
#define NWARPS 8
#define NHALF 16   // half-warps per CTA

// fp16 mirrors: entity table scaled by 256 (64 MB, L2-resident), relation table unscaled
__device__ __half g_entH[(size_t)NUM_ENTITIES * D];
__device__ __half g_relH[NUM_RELATIONS * D];

__global__ void convert_kernel(const float* __restrict__ ent, const float* __restrict__ rel) {
    // 15625 blocks * 256 threads * 8 elems = 32,000,000 = NUM_ENTITIES*D exactly
    size_t base = ((size_t)blockIdx.x * 256 + threadIdx.x) * 8;
    float4 a = __ldcs((const float4*)(ent + base));
    float4 b = __ldcs((const float4*)(ent + base + 4));
    __half2 p0 = __floats2half2_rn(a.x * 256.0f, a.y * 256.0f);
    __half2 p1 = __floats2half2_rn(a.z * 256.0f, a.w * 256.0f);
    __half2 p2 = __floats2half2_rn(b.x * 256.0f, b.y * 256.0f);
    __half2 p3 = __floats2half2_rn(b.z * 256.0f, b.w * 256.0f);
    uint4 pk;
    pk.x = *(unsigned*)&p0; pk.y = *(unsigned*)&p1;
    pk.z = *(unsigned*)&p2; pk.w = *(unsigned*)&p3;
    *(uint4*)(g_entH + base) = pk;
    if (blockIdx.x == 0) {
        for (int i = threadIdx.x; i < NUM_RELATIONS * D; i += 256)
            g_relH[i] = __float2half(rel[i]);
    }
}

__device__ __forceinline__ uint2 ldcg_u2(const void* p) {
    uint2 v;
    asm volatile("ld.global.cg.v2.u32 {%0,%1}, [%2];" : "=r"(v.x), "=r"(v.y) : "l"(p));
    return v;
}

__device__ __forceinline__ float4 h4_to_f4(uint2 u) {
    float2 a = __half22float2(*reinterpret_cast<__half2*>(&u.x));
    float2 b = __half22float2(*reinterpret_cast<__half2*>(&u.y));
    return make_float4(a.x, a.y, b.x, b.y);
}

__global__ __launch_bounds__(NTHREADS, 6)
void ripplenet_kernel(const int* __restrict__ item_ids,
                      const int* __restrict__ h0, const int* __restrict__ r0, const int* __restrict__ t0,
                      const int* __restrict__ h1, const int* __restrict__ r1, const int* __restrict__ t1,
                      const float* __restrict__ ent,
                      const float* __restrict__ W0, const float* __restrict__ W1,
                      float* __restrict__ out)
{
    const int b    = blockIdx.x;
    const int tid  = threadIdx.x;
    const int lane = tid & 31;
    const int w    = tid >> 5;
    const int half = lane >> 4;      // which slot of the lane-pair
    const int hl   = lane & 15;      // lane within half-warp: dims [4*hl, 4*hl+4)

    __shared__ __align__(16) float s_item[D];
    __shared__ __align__(16) float s_x[D];
    __shared__ int   s_hidx[2][M];
    __shared__ int   s_ridx[2][M];
    __shared__ int   s_tidx[2][M];
    __shared__ float s_esum[NHALF];
    __shared__ __align__(16) float s_o[NHALF][D];

    // stage BOTH hops' indices once, coalesced
    s_hidx[0][tid] = h0[(size_t)b * M + tid];
    s_ridx[0][tid] = r0[(size_t)b * M + tid];
    s_tidx[0][tid] = t0[(size_t)b * M + tid];
    s_hidx[1][tid] = h1[(size_t)b * M + tid];
    s_ridx[1][tid] = r1[(size_t)b * M + tid];
    s_tidx[1][tid] = t1[(size_t)b * M + tid];

    // load item embedding (fp32 original — exact)
    if (tid < D) {
        size_t row = (size_t)item_ids[b] * D;
        s_item[tid] = ent[row + tid];
    }
    __syncthreads();

    for (int hop = 0; hop < 2; hop++) {
        const float* W = hop ? W1 : W0;
        const int* hIdx = s_hidx[hop];
        const int* rIdx = s_ridx[hop];
        const int* tIdx = s_tidx[hop];

        // per-lane item chunk (4 dims), pre-scaled by 2^-8 to undo ent scaling
        float4 itv = *(const float4*)(s_item + 4 * hl);
        itv.x *= 0.00390625f; itv.y *= 0.00390625f;
        itv.z *= 0.00390625f; itv.w *= 0.00390625f;

        // ---- fused: logits + streaming (unnormalized) softmax + t-accumulate ----
        // all three row gathers are fp16: one 128B wavefront each per half-warp.
        float4 acc = make_float4(0.0f, 0.0f, 0.0f, 0.0f);
        float  esum = 0.0f;
        #pragma unroll 4
        for (int i = w; i < M / 2; i += NWARPS) {
            int m = 2 * i + half;
            uint2 tvp = ldcg_u2(g_entH + (size_t)tIdx[m] * D + 4 * hl);
            uint2 hvp = ldcg_u2(g_entH + (size_t)hIdx[m] * D + 4 * hl);
            uint2 rvp = *(const uint2*)(g_relH + rIdx[m] * D + 4 * hl);
            float4 hv = h4_to_f4(hvp);
            float4 rv = h4_to_f4(rvp);
            // logit: (h*256) * r * (item/256) == h*r*item
            float p = hv.x * rv.x * itv.x + hv.y * rv.y * itv.y
                    + hv.z * rv.z * itv.z + hv.w * rv.w * itv.w;
            #pragma unroll
            for (int s = 8; s; s >>= 1) p += __shfl_xor_sync(0xffffffffu, p, s);
            float e = __expf(p);   // |logit| << 1 — no max-shift needed
            float4 tv = h4_to_f4(tvp);   // scaled by 256; undone at normalization
            esum += e;
            acc.x += e * tv.x;
            acc.y += e * tv.y;
            acc.z += e * tv.z;
            acc.w += e * tv.w;
        }
        *(float4*)(&s_o[2 * w + half][4 * hl]) = acc;
        if (hl == 0) s_esum[2 * w + half] = esum;
        __syncthreads();

        // ---- x = item + o_unnorm / (sum_exp * 256) ----
        if (tid < D) {
            float o = 0.0f;
            #pragma unroll
            for (int hw = 0; hw < NHALF; hw++) o += s_o[hw][tid];
            float es = 0.0f;
            #pragma unroll
            for (int hw = 0; hw < NHALF; hw++) es += s_esum[hw];
            s_x[tid] = s_item[tid] + o * (0.00390625f / es);
        }
        __syncthreads();

        // ---- item = x @ W^T : item[j] = sum_i x[i] * W[j*D + i] ----
        if (tid < D) {
            const float4* Wr = (const float4*)(W + tid * D);
            float a = 0.0f;
            #pragma unroll
            for (int i = 0; i < D / 4; i++) {
                float4 wv = __ldg(Wr + i);
                a += s_x[4*i]   * wv.x + s_x[4*i+1] * wv.y
                   + s_x[4*i+2] * wv.z + s_x[4*i+3] * wv.w;
            }
            s_item[tid] = a;
        }
        __syncthreads();
    }

    // ---- final: out[b] = sum_d item[d] ----
    if (w == 0) {
        float v = s_item[lane] + s_item[lane + 32];
        #pragma unroll
        for (int s = 16; s; s >>= 1) v += __shfl_xor_sync(0xffffffffu, v, s);
        if (lane == 0) out[b] = v;
    }
}

extern "C" void kernel_launch(void* const* d_in, const int* in_sizes, int n_in,
                              void* d_out, int out_size)
{
    const int*   item_ids = (const int*)d_in[0];
    const int*   h0       = (const int*)d_in[1];
    const int*   r0       = (const int*)d_in[2];
    const int*   t0       = (const int*)d_in[3];
    const int*   h1       = (const int*)d_in[4];
    const int*   r1       = (const int*)d_in[5];
    const int*   t1       = (const int*)d_in[6];
    const float* ent      = (const float*)d_in[7];
    const float* rel      = (const float*)d_in[8];
    const float* W0       = (const float*)d_in[9];
    const float* W1       = (const float*)d_in[10];
    float*       out      = (float*)d_out;

    convert_kernel<<<15625, 256>>>(ent, rel);
    ripplenet_kernel<<<4096, NTHREADS>>>(item_ids, h0, r0, t0, h1, r1, t1,
                                         ent, W0, W1, out);
}